// round 4
// baseline (speedup 1.0000x reference)
#include <cuda_runtime.h>

#define BB 8
#define QQ 2048
#define GG 128
#define CC 512

// Transposed cost scratch: costT[b][g][q], fp32 (identical bits to final_cost)
__device__ float g_costT[BB * GG * QQ];

// ---------------------------------------------------------------------------
// Kernel 1: fused cost computation + transpose.
// Mirrors JAX eager fp32 op-by-op (no FMA contraction, exp-based sigmoid,
// pow(x,2) -> x*x, left-assoc multiply chains).
// ---------------------------------------------------------------------------
__global__ __launch_bounds__(256) void cost_kernel(
    const float* __restrict__ prob,     // [B][Q][C]
    const float* __restrict__ center,   // [B][Q][G]
    const float* __restrict__ size_,    // [B][Q][G]
    const float* __restrict__ gious,    // [B][Q][G]
    const void*  __restrict__ labels_v, // [B][G] int32 (default) or int64
    int labels_i64,
    float* __restrict__ fc)             // [B][Q][G]  (output region)
{
    __shared__ float tile[32][33];
    const int b  = blockIdx.z;
    const int g0 = blockIdx.x * 32;
    const int q0 = blockIdx.y * 32;
    const int tx = threadIdx.x;   // g within tile
    const int ty = threadIdx.y;   // q group (8 rows, loop 4x)

    const int g = g0 + tx;
    int cls;
    if (labels_i64) cls = (int)((const long long*)labels_v)[b * GG + g];
    else            cls = ((const int*)labels_v)[b * GG + g];

#pragma unroll
    for (int r = 0; r < 4; ++r) {
        const int q = q0 + ty + r * 8;
        const size_t bq = (size_t)b * QQ + q;
        const float x = prob[bq * CC + cls];

        // p = sigmoid(x) = 1 / (1 + exp(-x))
        const float p = __fdiv_rn(1.0f, __fadd_rn(1.0f, expf(-x)));

        // neg = (1-ALPHA) * p^2 * -log1p(-(p - 1e-8))
        const float t0  = __fsub_rn(p, 1e-8f);
        const float neg = __fmul_rn(__fmul_rn(0.75f, __fmul_rn(p, p)),
                                    -log1pf(-t0));
        // pos = ALPHA * (1-p)^2 * -log(p + 1e-8)
        const float omp = __fsub_rn(1.0f, p);
        const float pos = __fmul_rn(__fmul_rn(0.25f, __fmul_rn(omp, omp)),
                                    -logf(__fadd_rn(p, 1e-8f)));
        const float diff = __fsub_rn(pos, neg);

        const size_t idx = bq * GG + g;
        // W_CLASS*diff + W_CENTER*center + W_SIZE*size + W_GIOU*(-gious)
        float cost = __fmul_rn(2.0f, diff);
        cost = __fadd_rn(cost, __fmul_rn(5.0f, center[idx]));
        cost = __fadd_rn(cost, __fmul_rn(1.0f, size_[idx]));
        cost = __fadd_rn(cost, __fmul_rn(2.0f, -gious[idx]));

        fc[idx] = cost;
        tile[ty + r * 8][tx] = cost;   // tile[q_local][g_local]
    }
    __syncthreads();

    // costT[b][g][q], coalesced over q (tx indexes q now)
#pragma unroll
    for (int r = 0; r < 4; ++r) {
        const int gl = ty + r * 8;
        g_costT[((size_t)b * GG + (g0 + gl)) * QQ + (q0 + tx)] = tile[tx][gl];
    }
}

// ---------------------------------------------------------------------------
// Kernel 2: exact replica of the reference _lsa (including its discarded
// minv1/way1 copies: a potential-updating greedy chain whose final free
// column is assigned to the ORIGINAL row i). One block per batch, fp64
// arithmetic in numpy-identical order, first-index ties in argmin.
// ---------------------------------------------------------------------------
#define MCOL QQ

__global__ __launch_bounds__(1024, 1) void lsa_kernel(
    const void* __restrict__ nactual_v,
    int n_i64,
    float* __restrict__ out_inds_f32,     // mode A: f32 indices (or null)
    long long* __restrict__ out_inds_i64, // mode B: int64 indices (or null)
    float* __restrict__ out_mask)         // [B][Q]
{
    __shared__ double v[MCOL + 1];
    __shared__ double u[GG + 1];
    __shared__ short  p[MCOL + 1];
    __shared__ unsigned char used[MCOL + 1];
    __shared__ double s_delta;
    __shared__ int    s_j1;
    __shared__ int    s_i0;
    __shared__ double s_ui0;
    __shared__ double wval[32];
    __shared__ int    widx[32];

    const int b = blockIdx.x;
    const int t = threadIdx.x;
    int n;
    if (n_i64) n = (int)((const long long*)nactual_v)[b];
    else       n = ((const int*)nactual_v)[b];
    if (n < 0) n = 0;
    if (n > GG) n = GG;
    const float* Cb = g_costT + (size_t)b * GG * MCOL;

    for (int j = t; j <= MCOL; j += 1024) { v[j] = 0.0; p[j] = 0; }
    if (t <= GG) u[t] = 0.0;
    __syncthreads();

    for (int i = 1; i <= n; ++i) {
        for (int j = t; j <= MCOL; j += 1024) used[j] = 0;
        if (t == 0) p[0] = (short)i;
        __syncthreads();

        int j0 = 0;
        while (true) {
            if (t == 0) {
                used[j0] = 1;
                const int i0 = p[j0];
                s_i0  = i0;
                s_ui0 = u[i0];
            }
            __syncthreads();
            const int    i0  = s_i0;
            const double ui0 = s_ui0;
            const float* row = Cb + (size_t)(i0 - 1) * MCOL;

            // cur = ((double)C[i0-1][j-1] - u[i0]) - v[j], free columns only.
            double best  = 1e300;
            int    bestj = MCOL + 2;
#pragma unroll
            for (int k = 0; k < 2; ++k) {
                const int j = t + 1 + k * 1024;   // j in [1..2048]
                if (!used[j]) {
                    const double cur = ((double)row[j - 1] - ui0) - v[j];
                    if (cur < best) { best = cur; bestj = j; }  // smaller j on tie
                }
            }
            const unsigned fullm = 0xffffffffu;
            for (int off = 16; off; off >>= 1) {
                const double ov = __shfl_down_sync(fullm, best, off);
                const int    oi = __shfl_down_sync(fullm, bestj, off);
                if (ov < best || (ov == best && oi < bestj)) { best = ov; bestj = oi; }
            }
            if ((t & 31) == 0) { wval[t >> 5] = best; widx[t >> 5] = bestj; }
            __syncthreads();
            if (t < 32) {
                best = wval[t]; bestj = widx[t];
                for (int off = 16; off; off >>= 1) {
                    const double ov = __shfl_down_sync(fullm, best, off);
                    const int    oi = __shfl_down_sync(fullm, bestj, off);
                    if (ov < best || (ov == best && oi < bestj)) { best = ov; bestj = oi; }
                }
                if (t == 0) { s_delta = best; s_j1 = bestj; }
            }
            __syncthreads();
            const double delta = s_delta;
            const int    j1    = s_j1;

            // u[p[used]] += delta (distinct rows -> race-free), v[used] -= delta
            for (int j = t; j <= MCOL; j += 1024) {
                if (used[j]) { u[p[j]] += delta; v[j] -= delta; }
            }
            __syncthreads();

            j0 = j1;
            if (p[j0] == 0) break;
        }
        // degenerate augmentation (way == 0 in reference): column -> row i
        if (t == 0) p[j0] = (short)i;
        __syncthreads();
    }

    // Emit per-proposal gt index + matched mask
    for (int j = t + 1; j <= MCOL; j += 1024) {
        const int    r = p[j];
        const size_t o = (size_t)b * MCOL + (j - 1);
        if (out_inds_f32) out_inds_f32[o] = (r > 0) ? (float)(r - 1) : 0.0f;
        if (out_inds_i64) out_inds_i64[o] = (r > 0) ? (long long)(r - 1) : 0LL;
        out_mask[o] = (r > 0) ? 1.0f : 0.0f;
    }
}

// ---------------------------------------------------------------------------
extern "C" void kernel_launch(void* const* d_in, const int* in_sizes, int n_in,
                              void* d_out, int out_size) {
    const float* prob    = (const float*)d_in[0];
    const float* center  = (const float*)d_in[1];
    const float* size_   = (const float*)d_in[2];
    const float* gious   = (const float*)d_in[3];
    const void*  labels  = d_in[4];   // int32 (jax default x64-disabled) or int64
    const void*  nactual = d_in[5];

    float*     out_f32  = (float*)d_out;
    float*     inds_f32 = nullptr;
    long long* inds_i64 = nullptr;
    float*     mask;
    float*     fc;
    int i64_world = 0;

    if (out_size == 2146304) {
        // x64-enabled world: byte concat int64 inds | f32 mask | f32 final_cost
        i64_world = 1;
        inds_i64 = (long long*)d_out;
        mask = out_f32 + 32768;
        fc   = out_f32 + 49152;
    } else {
        // default (x64 disabled): int32 inds (cast/compared as f32 slots) |
        // f32 mask | f32 final_cost — 4-byte slots: 16384 | 16384 | 2097152
        inds_f32 = out_f32;
        mask = out_f32 + BB * QQ;
        fc   = out_f32 + 2 * BB * QQ;
    }

    dim3 cgrid(GG / 32, QQ / 32, BB);
    dim3 cblk(32, 8);
    cost_kernel<<<cgrid, cblk>>>(prob, center, size_, gious, labels, i64_world, fc);

    lsa_kernel<<<BB, 1024>>>(nactual, i64_world, inds_f32, inds_i64, mask);
}

// round 5
// speedup vs baseline: 1.3835x; 1.3835x over previous
#include <cuda_runtime.h>
#include <math_constants.h>
#include <float.h>

#define BB 8
#define QQ 2048
#define GG 128
#define CC 512

#define TLSA 256              // solver threads per block
#define KC   (QQ / TLSA)      // 8 contiguous columns per thread

// Transposed cost scratch: costT[b][g][q], fp32 (identical bits to final_cost)
__device__ float g_costT[BB * GG * QQ];

// ---------------------------------------------------------------------------
// Kernel 1: fused cost computation + transpose (unchanged: bit-exact vs ref).
// ---------------------------------------------------------------------------
__global__ __launch_bounds__(256) void cost_kernel(
    const float* __restrict__ prob,     // [B][Q][C]
    const float* __restrict__ center,   // [B][Q][G]
    const float* __restrict__ size_,    // [B][Q][G]
    const float* __restrict__ gious,    // [B][Q][G]
    const void*  __restrict__ labels_v, // [B][G] int32 (default) or int64
    int labels_i64,
    float* __restrict__ fc)             // [B][Q][G]  (output region)
{
    __shared__ float tile[32][33];
    const int b  = blockIdx.z;
    const int g0 = blockIdx.x * 32;
    const int q0 = blockIdx.y * 32;
    const int tx = threadIdx.x;
    const int ty = threadIdx.y;

    const int g = g0 + tx;
    int cls;
    if (labels_i64) cls = (int)((const long long*)labels_v)[b * GG + g];
    else            cls = ((const int*)labels_v)[b * GG + g];

#pragma unroll
    for (int r = 0; r < 4; ++r) {
        const int q = q0 + ty + r * 8;
        const size_t bq = (size_t)b * QQ + q;
        const float x = prob[bq * CC + cls];

        const float p = __fdiv_rn(1.0f, __fadd_rn(1.0f, expf(-x)));

        const float t0  = __fsub_rn(p, 1e-8f);
        const float neg = __fmul_rn(__fmul_rn(0.75f, __fmul_rn(p, p)),
                                    -log1pf(-t0));
        const float omp = __fsub_rn(1.0f, p);
        const float pos = __fmul_rn(__fmul_rn(0.25f, __fmul_rn(omp, omp)),
                                    -logf(__fadd_rn(p, 1e-8f)));
        const float diff = __fsub_rn(pos, neg);

        const size_t idx = bq * GG + g;
        float cost = __fmul_rn(2.0f, diff);
        cost = __fadd_rn(cost, __fmul_rn(5.0f, center[idx]));
        cost = __fadd_rn(cost, __fmul_rn(1.0f, size_[idx]));
        cost = __fadd_rn(cost, __fmul_rn(2.0f, -gious[idx]));

        fc[idx] = cost;
        tile[ty + r * 8][tx] = cost;
    }
    __syncthreads();

#pragma unroll
    for (int r = 0; r < 4; ++r) {
        const int gl = ty + r * 8;
        g_costT[((size_t)b * GG + (g0 + gl)) * QQ + (q0 + tx)] = tile[tx][gl];
    }
}

// ---------------------------------------------------------------------------
// Kernel 2: exact replica of the reference degenerate JV, restructured:
//  - deferred u/v updates (suffix-sum of deltas, applied at row end)
//  - per-thread register ownership of 8 contiguous columns (v64/v32/mask)
//  - 1 barrier per chain iteration (parity double-buffered leader slots)
//  - fp32 prefilter with sound error bound -> fp64 evaluated on ~1 col/thread
// Selection and delta values are bit-identical to the full-fp64 scan.
// ---------------------------------------------------------------------------
__global__ __launch_bounds__(TLSA, 1) void lsa_kernel(
    const void* __restrict__ nactual_v,
    int n_i64,
    float* __restrict__ out_inds_f32,
    long long* __restrict__ out_inds_i64,
    float* __restrict__ out_mask)
{
    __shared__ double u[GG + 1];
    __shared__ short  p[QQ + 1];
    __shared__ double sval[2][TLSA / 32];
    __shared__ int    sidx[2][TLSA / 32];
    __shared__ short  ccols[GG + 4];
    __shared__ double cA[GG + 4];

    const int b = blockIdx.x;
    const int t = threadIdx.x;
    int n;
    if (n_i64) n = (int)((const long long*)nactual_v)[b];
    else       n = ((const int*)nactual_v)[b];
    if (n < 0) n = 0;
    if (n > GG) n = GG;

    const float* Cb = g_costT + (size_t)b * GG * QQ;
    const int base = t * KC;            // owns columns base+1 .. base+KC (1-idx)

    double v64[KC];
    float  v32[KC];
#pragma unroll
    for (int k = 0; k < KC; ++k) { v64[k] = 0.0; v32[k] = 0.0f; }

    for (int j = t; j <= QQ; j += TLSA) p[j] = 0;
    for (int i = t; i <= GG; i += TLSA) u[i] = 0.0;
    __syncthreads();

    double UVmax = 0.0;   // sound bound on max(|u|,|v|): sum of per-row bumps

    for (int i = 1; i <= n; ++i) {
        unsigned mask = (1u << KC) - 1u;   // my free columns this row
        int    i0 = i;
        double S  = 0.0;
        int    len = 0;
        int    parity = 0;
        int    j1 = 0;

        while (true) {
            const double ui0 = u[i0];
            const float  u32 = (float)ui0;
            const float* row = Cb + (size_t)(i0 - 1) * QQ + base;
            const float4 r0 = *(const float4*)(row);
            const float4 r1 = *(const float4*)(row + 4);
            float c32[KC] = { r0.x, r0.y, r0.z, r0.w, r1.x, r1.y, r1.z, r1.w };

            // fp32 pass: local free min
            float cur32[KC];
            float lmin = CUDART_INF_F;
#pragma unroll
            for (int k = 0; k < KC; ++k) {
                cur32[k] = __fsub_rn(__fsub_rn(c32[k], u32), v32[k]);
                if ((mask >> k) & 1) lmin = fminf(lmin, cur32[k]);
            }
            // sound fp32->fp64 window: eps*(2Cmax + 5*UVmax), doubled
            const float tau = (float)(1.2e-7 * (100.0 + 6.0 * UVmax));

            // fp64 pass: only candidates inside the window (ascending k ->
            // smallest-column tie-break preserved)
            double best  = DBL_MAX;
            int    bestj = 1 << 30;
#pragma unroll
            for (int k = 0; k < KC; ++k) {
                if (((mask >> k) & 1) && cur32[k] <= lmin + tau) {
                    const double cur = ((double)c32[k] - ui0) - v64[k];
                    if (cur < best) { best = cur; bestj = base + k + 1; }
                }
            }

            // warp pair-reduce (min value, smallest index on exact tie)
            const unsigned fm = 0xffffffffu;
#pragma unroll
            for (int off = 16; off; off >>= 1) {
                const double ov = __shfl_down_sync(fm, best, off);
                const int    oi = __shfl_down_sync(fm, bestj, off);
                if (ov < best || (ov == best && oi < bestj)) { best = ov; bestj = oi; }
            }
            if ((t & 31) == 0) { sval[parity][t >> 5] = best; sidx[parity][t >> 5] = bestj; }
            __syncthreads();   // the only barrier per iteration

            double delta = sval[parity][0];
            int    jj    = sidx[parity][0];
#pragma unroll
            for (int w = 1; w < TLSA / 32; ++w) {
                const double ov = sval[parity][w];
                const int    oi = sidx[parity][w];
                if (ov < delta || (ov == delta && oi < jj)) { delta = ov; jj = oi; }
            }
            parity ^= 1;

            j1 = jj;
            S += delta;
            const int pj = p[j1];                 // stable during chain
            if (((j1 - 1) >> 3) == t)             // mark used locally
                mask &= ~(1u << ((j1 - 1) & (KC - 1)));
            if (pj == 0) break;                   // free column -> chain ends
            if (t == 0) { ccols[len] = (short)j1; cA[len] = S; }
            ++len;
            i0 = pj;
        }

        // ---- row end: apply deferred potential updates ----
        __syncthreads();                           // chain arrays visible
        if (t == 0) { u[i] += S; p[j1] = (short)i; }
        if (t < len) { const int jc = ccols[t]; u[p[jc]] += S - cA[t]; }

        double bump = fabs(S);
        for (int c = 0; c < len; ++c) {
            const int    jc  = ccols[c];
            const double adj = S - cA[c];
            bump = fmax(bump, fabs(adj));
            const int rel = jc - 1 - base;
            if (rel >= 0 && rel < KC) {
#pragma unroll
                for (int k = 0; k < KC; ++k)
                    if (rel == k) { v64[k] -= adj; v32[k] = (float)v64[k]; }
            }
        }
        UVmax += bump;
        __syncthreads();                           // u/p/v settled for next row
    }

    // Emit per-proposal gt index + matched mask
    for (int j = t + 1; j <= QQ; j += TLSA) {
        const int    r = p[j];
        const size_t o = (size_t)b * QQ + (j - 1);
        if (out_inds_f32) out_inds_f32[o] = (r > 0) ? (float)(r - 1) : 0.0f;
        if (out_inds_i64) out_inds_i64[o] = (r > 0) ? (long long)(r - 1) : 0LL;
        out_mask[o] = (r > 0) ? 1.0f : 0.0f;
    }
}

// ---------------------------------------------------------------------------
extern "C" void kernel_launch(void* const* d_in, const int* in_sizes, int n_in,
                              void* d_out, int out_size) {
    const float* prob    = (const float*)d_in[0];
    const float* center  = (const float*)d_in[1];
    const float* size_   = (const float*)d_in[2];
    const float* gious   = (const float*)d_in[3];
    const void*  labels  = d_in[4];
    const void*  nactual = d_in[5];

    float*     out_f32  = (float*)d_out;
    float*     inds_f32 = nullptr;
    long long* inds_i64 = nullptr;
    float*     mask;
    float*     fc;
    int i64_world = 0;

    if (out_size == 2146304) {
        i64_world = 1;
        inds_i64 = (long long*)d_out;
        mask = out_f32 + 32768;
        fc   = out_f32 + 49152;
    } else {
        inds_f32 = out_f32;
        mask = out_f32 + BB * QQ;
        fc   = out_f32 + 2 * BB * QQ;
    }

    dim3 cgrid(GG / 32, QQ / 32, BB);
    dim3 cblk(32, 8);
    cost_kernel<<<cgrid, cblk>>>(prob, center, size_, gious, labels, i64_world, fc);

    lsa_kernel<<<BB, TLSA>>>(nactual, i64_world, inds_f32, inds_i64, mask);
}

// round 6
// speedup vs baseline: 4.4431x; 3.2114x over previous
#include <cuda_runtime.h>
#include <math_constants.h>
#include <float.h>

#define BB 8
#define QQ 2048
#define GG 128
#define CC 512

#define TLSA 256              // solver threads per block
#define NW   (TLSA / 32)      // warps
#define KC   (QQ / TLSA)      // 8 contiguous columns per thread

// Transposed cost scratch: costT[b][g][q], fp32 (identical bits to final_cost)
__device__ float g_costT[BB * GG * QQ];

// ---------------------------------------------------------------------------
// Kernel 1: fused cost computation + transpose (bit-exact vs reference).
// ---------------------------------------------------------------------------
__global__ __launch_bounds__(256) void cost_kernel(
    const float* __restrict__ prob,     // [B][Q][C]
    const float* __restrict__ center,   // [B][Q][G]
    const float* __restrict__ size_,    // [B][Q][G]
    const float* __restrict__ gious,    // [B][Q][G]
    const void*  __restrict__ labels_v, // [B][G] int32 (default) or int64
    int labels_i64,
    float* __restrict__ fc)             // [B][Q][G]  (output region)
{
    __shared__ float tile[32][33];
    const int b  = blockIdx.z;
    const int g0 = blockIdx.x * 32;
    const int q0 = blockIdx.y * 32;
    const int tx = threadIdx.x;
    const int ty = threadIdx.y;

    const int g = g0 + tx;
    int cls;
    if (labels_i64) cls = (int)((const long long*)labels_v)[b * GG + g];
    else            cls = ((const int*)labels_v)[b * GG + g];

#pragma unroll
    for (int r = 0; r < 4; ++r) {
        const int q = q0 + ty + r * 8;
        const size_t bq = (size_t)b * QQ + q;
        const float x = prob[bq * CC + cls];

        const float p = __fdiv_rn(1.0f, __fadd_rn(1.0f, expf(-x)));

        const float t0  = __fsub_rn(p, 1e-8f);
        const float neg = __fmul_rn(__fmul_rn(0.75f, __fmul_rn(p, p)),
                                    -log1pf(-t0));
        const float omp = __fsub_rn(1.0f, p);
        const float pos = __fmul_rn(__fmul_rn(0.25f, __fmul_rn(omp, omp)),
                                    -logf(__fadd_rn(p, 1e-8f)));
        const float diff = __fsub_rn(pos, neg);

        const size_t idx = bq * GG + g;
        float cost = __fmul_rn(2.0f, diff);
        cost = __fadd_rn(cost, __fmul_rn(5.0f, center[idx]));
        cost = __fadd_rn(cost, __fmul_rn(1.0f, size_[idx]));
        cost = __fadd_rn(cost, __fmul_rn(2.0f, -gious[idx]));

        fc[idx] = cost;
        tile[ty + r * 8][tx] = cost;
    }
    __syncthreads();

#pragma unroll
    for (int r = 0; r < 4; ++r) {
        const int gl = ty + r * 8;
        g_costT[((size_t)b * GG + (g0 + gl)) * QQ + (q0 + tx)] = tile[tx][gl];
    }
}

// ordered-float encode/decode (monotonic u32)
__device__ __forceinline__ unsigned ford(float x) {
    unsigned b = __float_as_uint(x);
    return b ^ ((b & 0x80000000u) ? 0xFFFFFFFFu : 0x80000000u);
}
__device__ __forceinline__ float funord(unsigned k) {
    unsigned b = (k & 0x80000000u) ? (k ^ 0x80000000u) : ~k;
    return __uint_as_float(b);
}

// ---------------------------------------------------------------------------
// Kernel 2: reference degenerate JV. Fast path reduces a packed
// (ordered-fp32(c-v32) , column) u64 (u[i0] uniform -> order-invariant);
// the winner's exact fp64 delta ((c-u)-v, reference order) is broadcast.
// A sound tau-window + __syncthreads_or detects any possible fp32/fp64
// disagreement; only then the full fp64 reduce runs. Bit-identical result.
// ---------------------------------------------------------------------------
__global__ __launch_bounds__(TLSA, 1) void lsa_kernel(
    const void* __restrict__ nactual_v,
    int n_i64,
    float* __restrict__ out_inds_f32,
    long long* __restrict__ out_inds_i64,
    float* __restrict__ out_mask)
{
    __shared__ double u[GG + 1];
    __shared__ short  p[QQ + 1];
    __shared__ unsigned long long slots[2][NW];
    __shared__ double s_delta[2];
    __shared__ double sv[NW];
    __shared__ int    si[NW];
    __shared__ short  ccols[GG + 4];
    __shared__ double cA[GG + 4];

    const int b = blockIdx.x;
    const int t = threadIdx.x;
    int n;
    if (n_i64) n = (int)((const long long*)nactual_v)[b];
    else       n = ((const int*)nactual_v)[b];
    if (n < 0) n = 0;
    if (n > GG) n = GG;

    const float* Cb = g_costT + (size_t)b * GG * QQ;
    const int base = t * KC;            // owns columns base+1 .. base+KC

    double v64[KC];
    float  v32[KC];
#pragma unroll
    for (int k = 0; k < KC; ++k) { v64[k] = 0.0; v32[k] = 0.0f; }

    for (int j = t; j <= QQ; j += TLSA) p[j] = 0;
    for (int i = t; i <= GG; i += TLSA) u[i] = 0.0;
    __syncthreads();

    double UVmax = 0.0;
    int par = 0;

    for (int i = 1; i <= n; ++i) {
        unsigned mask = (1u << KC) - 1u;
        int    i0 = i;
        double S  = 0.0;
        int    len = 0;
        int    jsel = 0;
        const float tau = (float)(1.2e-7 * (100.0 + 6.0 * UVmax));

        while (true) {
            const double ui0 = u[i0];
            const float* row = Cb + (size_t)(i0 - 1) * QQ + base;
            const float4 r0 = *(const float4*)(row);
            const float4 r1 = *(const float4*)(row + 4);
            const float c32[KC] = { r0.x, r0.y, r0.z, r0.w, r1.x, r1.y, r1.z, r1.w };

            // w = c - v32 (u[i0] uniform across columns -> same ordering)
            float w[KC];
            float lmin = CUDART_INF_F;
            int   lk   = 0;
#pragma unroll
            for (int k = 0; k < KC; ++k) {
                w[k] = __fsub_rn(c32[k], v32[k]);
                if (((mask >> k) & 1) && w[k] < lmin) { lmin = w[k]; lk = k; }
            }

            // packed (ordered-key, column) u64 reduce; lexicographic min
            unsigned long long pk =
                ((unsigned long long)ford(lmin) << 32) | (unsigned)(base + lk + 1);
            const unsigned fm = 0xffffffffu;
#pragma unroll
            for (int off = 16; off; off >>= 1) {
                const unsigned long long o = __shfl_down_sync(fm, pk, off);
                if (o < pk) pk = o;
            }
            if ((t & 31) == 0) slots[par][t >> 5] = pk;
            __syncthreads();                       // bar 1

            // register tree over NW=8 slots
            unsigned long long a0 = slots[par][0], a1 = slots[par][1];
            unsigned long long a2 = slots[par][2], a3 = slots[par][3];
            unsigned long long a4 = slots[par][4], a5 = slots[par][5];
            unsigned long long a6 = slots[par][6], a7 = slots[par][7];
            a0 = (a1 < a0) ? a1 : a0;  a2 = (a3 < a2) ? a3 : a2;
            a4 = (a5 < a4) ? a5 : a4;  a6 = (a7 < a6) ? a7 : a6;
            a0 = (a2 < a0) ? a2 : a0;  a4 = (a6 < a4) ? a6 : a4;
            a0 = (a4 < a0) ? a4 : a0;

            const int   jfast = (int)(a0 & 0xffffffffu);
            const float gw    = funord((unsigned)(a0 >> 32));

            // owner computes exact fp64 delta (reference op order)
            if (((jfast - 1) >> 3) == t) {
                const int kk = (jfast - 1) & (KC - 1);
                s_delta[par] = ((double)c32[kk] - ui0) - v64[kk];
            }

            // ambiguity: any OTHER free column within tau of the fp32 min
            const float thr = __fadd_rn(gw, tau);
            int flag = 0;
#pragma unroll
            for (int k = 0; k < KC; ++k) {
                if (((mask >> k) & 1) && (base + k + 1 != jfast) && w[k] <= thr)
                    flag = 1;
            }
            const int ambig = __syncthreads_or(flag);   // bar 2

            double delta;
            int    jj;
            if (!ambig) {
                delta = s_delta[par];
                jj    = jfast;
            } else {
                // exact full fp64 reduce (rare)
                double best  = DBL_MAX;
                int    bestj = 1 << 30;
#pragma unroll
                for (int k = 0; k < KC; ++k) {
                    if ((mask >> k) & 1) {
                        const double cur = ((double)c32[k] - ui0) - v64[k];
                        if (cur < best) { best = cur; bestj = base + k + 1; }
                    }
                }
#pragma unroll
                for (int off = 16; off; off >>= 1) {
                    const double ov = __shfl_down_sync(fm, best, off);
                    const int    oi = __shfl_down_sync(fm, bestj, off);
                    if (ov < best || (ov == best && oi < bestj)) { best = ov; bestj = oi; }
                }
                if ((t & 31) == 0) { sv[t >> 5] = best; si[t >> 5] = bestj; }
                __syncthreads();
                delta = sv[0]; jj = si[0];
#pragma unroll
                for (int wi = 1; wi < NW; ++wi) {
                    const double ov = sv[wi];
                    const int    oi = si[wi];
                    if (ov < delta || (ov == delta && oi < jj)) { delta = ov; jj = oi; }
                }
                __syncthreads();
            }
            par ^= 1;

            jsel = jj;
            S += delta;
            const int pj = p[jj];
            if (((jj - 1) >> 3) == t)
                mask &= ~(1u << ((jj - 1) & (KC - 1)));
            if (pj == 0) break;
            if (t == 0) { ccols[len] = (short)jj; cA[len] = S; }
            ++len;
            i0 = pj;
        }

        // ---- row end: apply deferred potential updates ----
        __syncthreads();
        if (t == 0) { u[i] += S; p[jsel] = (short)i; }
        if (t < len) { const int jc = ccols[t]; u[p[jc]] += S - cA[t]; }

        double bump = fabs(S);
        for (int c = 0; c < len; ++c) {
            const int    jc  = ccols[c];
            const double adj = S - cA[c];
            bump = fmax(bump, fabs(adj));
            const int rel = jc - 1 - base;
            if (rel >= 0 && rel < KC) {
#pragma unroll
                for (int k = 0; k < KC; ++k)
                    if (rel == k) { v64[k] -= adj; v32[k] = (float)v64[k]; }
            }
        }
        UVmax += bump;
        __syncthreads();
    }

    // Emit per-proposal gt index + matched mask
    for (int j = t + 1; j <= QQ; j += TLSA) {
        const int    r = p[j];
        const size_t o = (size_t)b * QQ + (j - 1);
        if (out_inds_f32) out_inds_f32[o] = (r > 0) ? (float)(r - 1) : 0.0f;
        if (out_inds_i64) out_inds_i64[o] = (r > 0) ? (long long)(r - 1) : 0LL;
        out_mask[o] = (r > 0) ? 1.0f : 0.0f;
    }
}

// ---------------------------------------------------------------------------
extern "C" void kernel_launch(void* const* d_in, const int* in_sizes, int n_in,
                              void* d_out, int out_size) {
    const float* prob    = (const float*)d_in[0];
    const float* center  = (const float*)d_in[1];
    const float* size_   = (const float*)d_in[2];
    const float* gious   = (const float*)d_in[3];
    const void*  labels  = d_in[4];
    const void*  nactual = d_in[5];

    float*     out_f32  = (float*)d_out;
    float*     inds_f32 = nullptr;
    long long* inds_i64 = nullptr;
    float*     mask;
    float*     fc;
    int i64_world = 0;

    if (out_size == 2146304) {
        i64_world = 1;
        inds_i64 = (long long*)d_out;
        mask = out_f32 + 32768;
        fc   = out_f32 + 49152;
    } else {
        inds_f32 = out_f32;
        mask = out_f32 + BB * QQ;
        fc   = out_f32 + 2 * BB * QQ;
    }

    dim3 cgrid(GG / 32, QQ / 32, BB);
    dim3 cblk(32, 8);
    cost_kernel<<<cgrid, cblk>>>(prob, center, size_, gious, labels, i64_world, fc);

    lsa_kernel<<<BB, TLSA>>>(nactual, i64_world, inds_f32, inds_i64, mask);
}

// round 8
// speedup vs baseline: 4.8579x; 1.0934x over previous
#include <cuda_runtime.h>
#include <math_constants.h>
#include <float.h>

#define BB 8
#define QQ 2048
#define GG 128
#define CC 512

#define TLSA 256              // solver threads per block
#define NW   (TLSA / 32)      // warps
#define KC   (QQ / TLSA)      // 8 contiguous columns per thread

// Transposed cost scratch: costT[b][g][q], fp32 (identical bits to final_cost)
__device__ float g_costT[BB * GG * QQ];

// ---------------------------------------------------------------------------
// Kernel 1: fused cost computation + transpose (bit-exact vs reference).
// ---------------------------------------------------------------------------
__global__ __launch_bounds__(256) void cost_kernel(
    const float* __restrict__ prob,     // [B][Q][C]
    const float* __restrict__ center,   // [B][Q][G]
    const float* __restrict__ size_,    // [B][Q][G]
    const float* __restrict__ gious,    // [B][Q][G]
    const void*  __restrict__ labels_v, // [B][G] int32 (default) or int64
    int labels_i64,
    float* __restrict__ fc)             // [B][Q][G]  (output region)
{
    __shared__ float tile[32][33];
    const int b  = blockIdx.z;
    const int g0 = blockIdx.x * 32;
    const int q0 = blockIdx.y * 32;
    const int tx = threadIdx.x;
    const int ty = threadIdx.y;

    const int g = g0 + tx;
    int cls;
    if (labels_i64) cls = (int)((const long long*)labels_v)[b * GG + g];
    else            cls = ((const int*)labels_v)[b * GG + g];

#pragma unroll
    for (int r = 0; r < 4; ++r) {
        const int q = q0 + ty + r * 8;
        const size_t bq = (size_t)b * QQ + q;
        const float x = prob[bq * CC + cls];

        const float p = __fdiv_rn(1.0f, __fadd_rn(1.0f, expf(-x)));

        const float t0  = __fsub_rn(p, 1e-8f);
        const float neg = __fmul_rn(__fmul_rn(0.75f, __fmul_rn(p, p)),
                                    -log1pf(-t0));
        const float omp = __fsub_rn(1.0f, p);
        const float pos = __fmul_rn(__fmul_rn(0.25f, __fmul_rn(omp, omp)),
                                    -logf(__fadd_rn(p, 1e-8f)));
        const float diff = __fsub_rn(pos, neg);

        const size_t idx = bq * GG + g;
        float cost = __fmul_rn(2.0f, diff);
        cost = __fadd_rn(cost, __fmul_rn(5.0f, center[idx]));
        cost = __fadd_rn(cost, __fmul_rn(1.0f, size_[idx]));
        cost = __fadd_rn(cost, __fmul_rn(2.0f, -gious[idx]));

        fc[idx] = cost;
        tile[ty + r * 8][tx] = cost;
    }
    __syncthreads();

#pragma unroll
    for (int r = 0; r < 4; ++r) {
        const int gl = ty + r * 8;
        g_costT[((size_t)b * GG + (g0 + gl)) * QQ + (q0 + tx)] = tile[tx][gl];
    }
}

// ordered-float encode/decode (monotonic u32)
__device__ __forceinline__ unsigned ford(float x) {
    unsigned b = __float_as_uint(x);
    return b ^ ((b & 0x80000000u) ? 0xFFFFFFFFu : 0x80000000u);
}
__device__ __forceinline__ float funord(unsigned k) {
    unsigned b = (k & 0x80000000u) ? (k ^ 0x80000000u) : ~k;
    return __uint_as_float(b);
}

// ---------------------------------------------------------------------------
// Kernel 2: reference degenerate JV. Single barrier per chain iteration:
//  - per-warp reduce via redux.sync.min.u32 on ordered-fp32 keys, ballot
//    picks lowest attaining lane (= smallest column, contiguous ownership)
//  - (min, second-min) pair per warp -> every thread computes the global
//    min, winner column, and ambiguity after ONE __syncthreads
//  - owner thread accumulates the exact fp64 chain sum S in shared s_S
//    (no delta broadcast); rare tau-ambiguous iterations take the exact
//    full-fp64 reduce. Selection bit-identical to a pure fp64 scan.
// ---------------------------------------------------------------------------
__global__ __launch_bounds__(TLSA, 1) void lsa_kernel(
    const void* __restrict__ nactual_v,
    int n_i64,
    float* __restrict__ out_inds_f32,
    long long* __restrict__ out_inds_i64,
    float* __restrict__ out_mask)
{
    __shared__ double u[GG + 1];
    __shared__ short  p[QQ + 1];
    __shared__ unsigned long long slots[2][NW];
    __shared__ unsigned m2s[2][NW];
    __shared__ double s_S;
    __shared__ double sv[NW];
    __shared__ int    si[NW];
    __shared__ short  ccols[GG + 4];
    __shared__ double cA[GG + 4];

    const int b = blockIdx.x;
    const int t = threadIdx.x;
    int n;
    if (n_i64) n = (int)((const long long*)nactual_v)[b];
    else       n = ((const int*)nactual_v)[b];
    if (n < 0) n = 0;
    if (n > GG) n = GG;

    const float* Cb = g_costT + (size_t)b * GG * QQ;
    const int base = t * KC;            // owns columns base+1 .. base+KC

    double v64[KC];
    float  v32[KC];
#pragma unroll
    for (int k = 0; k < KC; ++k) { v64[k] = 0.0; v32[k] = 0.0f; }

    for (int j = t; j <= QQ; j += TLSA) p[j] = 0;
    for (int i = t; i <= GG; i += TLSA) u[i] = 0.0;
    if (t == 0) s_S = 0.0;
    __syncthreads();

    double UVmax = 0.0;
    int par = 0;
    const unsigned fm = 0xffffffffu;
    const int lane = t & 31;
    const int wix  = t >> 5;

    for (int i = 1; i <= n; ++i) {
        unsigned mask = (1u << KC) - 1u;
        int    i0 = i;
        int    len = 0;
        int    jsel = 0;
        const float tau = (float)(1.2e-7 * (100.0 + 6.0 * UVmax));

        const float* row0 = Cb + (size_t)(i0 - 1) * QQ + base;
        float4 r0 = *(const float4*)(row0);
        float4 r1 = *(const float4*)(row0 + 4);

        while (true) {
            const double ui0 = u[i0];
            const float c32[KC] = { r0.x, r0.y, r0.z, r0.w, r1.x, r1.y, r1.z, r1.w };

            // local (min, second-min) over my free columns, ordered-uint keys
            unsigned key1 = 0xFFFFFFFFu, key2 = 0xFFFFFFFFu;
            int k1 = 0;
#pragma unroll
            for (int k = 0; k < KC; ++k) {
                const float w = __fsub_rn(c32[k], v32[k]);
                unsigned kk = ford(w);
                if (!((mask >> k) & 1)) kk = 0xFFFFFFFFu;
                if (kk < key1) { key2 = key1; key1 = kk; k1 = k; }
                else if (kk < key2) { key2 = kk; }
            }

            // warp reduce via redux: min, owner lane, second-min, winner col
            const unsigned m1 = __reduce_min_sync(fm, key1);
            const unsigned ball = __ballot_sync(fm, key1 == m1);
            const int owner_lane = __ffs(ball) - 1;
            const unsigned cand2 = (lane == owner_lane) ? key2 : key1;
            const unsigned m2 = __reduce_min_sync(fm, cand2);
            const int col1 = __shfl_sync(fm, base + k1 + 1, owner_lane);

            if (lane == 0) {
                slots[par][wix] = ((unsigned long long)m1 << 32) | (unsigned)col1;
                m2s[par][wix] = m2;
            }
            __syncthreads();                       // the single barrier

            // slot tree: global min + global second-min key
            unsigned long long a0 = slots[par][0];
#pragma unroll
            for (int wi = 1; wi < NW; ++wi) {
                const unsigned long long x = slots[par][wi];
                if (x < a0) a0 = x;
            }
            unsigned gsec = 0xFFFFFFFFu;
#pragma unroll
            for (int wi = 0; wi < NW; ++wi) {
                const unsigned long long x = slots[par][wi];
                const unsigned cnd = (x == a0) ? m2s[par][wi] : (unsigned)(x >> 32);
                if (cnd < gsec) gsec = cnd;
            }
            par ^= 1;

            const float gw = funord((unsigned)(a0 >> 32));
            const float gs = funord(gsec);                    // NaN if none
            const bool ambig = (gs <= __fadd_rn(gw, tau));    // NaN -> false

            int jj;
            double delta_fb = 0.0;
            bool fb = false;
            if (!ambig) {
                jj = (int)(a0 & 0xffffffffu);
            } else {
                // exact full fp64 reduce (rare; uniform branch)
                double best = DBL_MAX; int bestj = 1 << 30;
#pragma unroll
                for (int k = 0; k < KC; ++k) {
                    if ((mask >> k) & 1) {
                        const double cur = ((double)c32[k] - ui0) - v64[k];
                        if (cur < best) { best = cur; bestj = base + k + 1; }
                    }
                }
#pragma unroll
                for (int off = 16; off; off >>= 1) {
                    const double ov = __shfl_down_sync(fm, best, off);
                    const int    oi = __shfl_down_sync(fm, bestj, off);
                    if (ov < best || (ov == best && oi < bestj)) { best = ov; bestj = oi; }
                }
                if (lane == 0) { sv[wix] = best; si[wix] = bestj; }
                __syncthreads();
                double dd = sv[0]; int jjj = si[0];
#pragma unroll
                for (int wi = 1; wi < NW; ++wi) {
                    if (sv[wi] < dd || (sv[wi] == dd && si[wi] < jjj)) { dd = sv[wi]; jjj = si[wi]; }
                }
                __syncthreads();                   // protect sv/si reuse
                jj = jjj; delta_fb = dd; fb = true;
            }

            const int pj = p[jj];

            // prefetch next chain row as early as possible
            if (pj != 0) {
                const float* nr = Cb + (size_t)(pj - 1) * QQ + base;
                r0 = *(const float4*)(nr);
                r1 = *(const float4*)(nr + 4);
            }

            // chain-sum bookkeeping: owner thread (fast) / t0 (fallback)
            if (!fb) {
                if (((jj - 1) >> 3) == t) {
                    const int kk2 = (jj - 1) & (KC - 1);
                    const double delta = ((double)c32[kk2] - ui0) - v64[kk2];
                    const double Snew = s_S + delta;
                    if (pj != 0) { ccols[len] = (short)jj; cA[len] = Snew; }
                    s_S = Snew;
                }
            } else if (t == 0) {
                const double Snew = s_S + delta_fb;
                if (pj != 0) { ccols[len] = (short)jj; cA[len] = Snew; }
                s_S = Snew;
            }

            if (((jj - 1) >> 3) == t)
                mask &= ~(1u << ((jj - 1) & (KC - 1)));

            if (pj == 0) { jsel = jj; break; }
            ++len;
            i0 = pj;
        }

        // ---- row end: apply deferred potential updates ----
        __syncthreads();
        const double S = s_S;
        if (t == 0) { u[i] += S; p[jsel] = (short)i; }
        if (t < len) { u[p[ccols[t]]] += S - cA[t]; }

        double bump = fabs(S);
        for (int c = 0; c < len; ++c) {
            const int    jc  = ccols[c];
            const double adj = S - cA[c];
            bump = fmax(bump, fabs(adj));
            const int rel = jc - 1 - base;
            if (rel >= 0 && rel < KC) {
#pragma unroll
                for (int k = 0; k < KC; ++k)
                    if (rel == k) { v64[k] -= adj; v32[k] = (float)v64[k]; }
            }
        }
        UVmax += bump;
        __syncthreads();
        if (t == 0) s_S = 0.0;
    }

    // Emit per-proposal gt index + matched mask
    for (int j = t + 1; j <= QQ; j += TLSA) {
        const int    r = p[j];
        const size_t o = (size_t)b * QQ + (j - 1);
        if (out_inds_f32) out_inds_f32[o] = (r > 0) ? (float)(r - 1) : 0.0f;
        if (out_inds_i64) out_inds_i64[o] = (r > 0) ? (long long)(r - 1) : 0LL;
        out_mask[o] = (r > 0) ? 1.0f : 0.0f;
    }
}

// ---------------------------------------------------------------------------
extern "C" void kernel_launch(void* const* d_in, const int* in_sizes, int n_in,
                              void* d_out, int out_size) {
    const float* prob    = (const float*)d_in[0];
    const float* center  = (const float*)d_in[1];
    const float* size_   = (const float*)d_in[2];
    const float* gious   = (const float*)d_in[3];
    const void*  labels  = d_in[4];
    const void*  nactual = d_in[5];

    float*     out_f32  = (float*)d_out;
    float*     inds_f32 = nullptr;
    long long* inds_i64 = nullptr;
    float*     mask;
    float*     fc;
    int i64_world = 0;

    if (out_size == 2146304) {
        i64_world = 1;
        inds_i64 = (long long*)d_out;
        mask = out_f32 + 32768;
        fc   = out_f32 + 49152;
    } else {
        inds_f32 = out_f32;
        mask = out_f32 + BB * QQ;
        fc   = out_f32 + 2 * BB * QQ;
    }

    dim3 cgrid(GG / 32, QQ / 32, BB);
    dim3 cblk(32, 8);
    cost_kernel<<<cgrid, cblk>>>(prob, center, size_, gious, labels, i64_world, fc);

    lsa_kernel<<<BB, TLSA>>>(nactual, i64_world, inds_f32, inds_i64, mask);
}